// round 13
// baseline (speedup 1.0000x reference)
#include <cuda_runtime.h>

// Layout constants (columns within the 208-wide feature dim)
#define NCOLS        208
#define OPCODE_START 88
#define AX_START     163
#define PC_START     171
#define IMM_START    195
#define BRANCH_TAKEN 203
// opcode offsets
#define OP_JMP 2
#define OP_BZ  4
#define OP_BNZ 5

// Persistent single-wave grid: 4 blocks/SM x 148 SMs. launch_bounds(256,4)
// caps regs at 64 -> co-residency of all 592 blocks is guaranteed on any
// sm_103a part (148 or 152 SMs), so the grid barrier below cannot deadlock.
#define GRID    592
#define THREADS 256
#define NWARPS  (GRID * (THREADS / 32))

__device__ unsigned g_partials[GRID];
// Monotone arrival counter. Zero at module load; NEVER reset. Each kernel
// execution performs exactly GRID atomicAdds, so a block computes its replay's
// barrier target from its own ticket: target = ticket - ticket%GRID + GRID.
// Deterministic across the correctness run and every graph replay.
__device__ unsigned g_arrive;

__global__ void __launch_bounds__(THREADS, 4)
fused_kernel(const float* __restrict__ x, float* __restrict__ y, int nrows)
{
    __shared__ unsigned s_warp[THREADS / 32];
    __shared__ unsigned s_target;
    __shared__ unsigned s_flags;

    const int tid  = threadIdx.x;
    const int gtid = blockIdx.x * THREADS + tid;

    // ---------------- Phase A: opcode scan (1 row/thread, grid-stride) -----
    unsigned f = 0u;
    for (int r = gtid; r < nrows; r += GRID * THREADS) {
        const float* xr = x + (size_t)r * NCOLS + OPCODE_START;
        if (xr[OP_JMP] > 0.5f) f |= 1u;
        if (xr[OP_BZ]  > 0.5f) f |= 2u;
        if (xr[OP_BNZ] > 0.5f) f |= 4u;
    }
    f = __reduce_or_sync(0xFFFFFFFFu, f);
    if ((tid & 31) == 0) s_warp[tid >> 5] = f;
    __syncthreads();

    if (tid == 0) {
        unsigned bf = 0u;
        #pragma unroll
        for (int w = 0; w < THREADS / 32; w++) bf |= s_warp[w];
        g_partials[blockIdx.x] = bf;        // unconditional -> no reset needed
        __threadfence();                    // release partial before arriving
        unsigned ticket = atomicAdd(&g_arrive, 1u);
        s_target = ticket - (ticket % GRID) + GRID;
    }
    __syncthreads();

    // ---------------- Reset-free grid barrier ------------------------------
    if (tid == 0) {
        const unsigned target = s_target;
        unsigned cur;
        do {
            asm volatile("ld.global.acquire.gpu.u32 %0, [%1];"
                         : "=r"(cur) : "l"(&g_arrive));
        } while (cur < target);
    }
    __syncthreads();   // acquire-ld + syncthreads orders partials for the block

    // OR the 592 partials (warp 0, L2-hot broadcast reads)
    if (tid < 32) {
        unsigned acc = 0u;
        for (int i = tid; i < GRID; i += 32) acc |= g_partials[i];
        acc = __reduce_or_sync(0xFFFFFFFFu, acc);
        if (tid == 0) s_flags = acc;
    }
    __syncthreads();
    const unsigned flags = s_flags;

    const bool jmp = (flags & 1u) != 0u;
    const bool bz  = (flags & 2u) != 0u;
    const bool bnz = (flags & 4u) != 0u;

    // ---------------- Phase B: warp-per-row copy + in-register patch -------
    const int gwarp = gtid >> 5;
    const int lane  = tid & 31;

    for (int row = gwarp; row < nrows; row += NWARPS) {
        const float*  xr = x + (size_t)row * NCOLS;
        float*        yr = y + (size_t)row * NCOLS;
        const float4* xv = (const float4*)xr;
        float4*       yv = (float4*)yr;

        // Bulk row copy: 52 float4 chunks (208 floats).
        float4 v0 = xv[lane];
        float4 v1;
        if (lane < 20) v1 = xv[32 + lane];

        if (flags != 0u) {
            // Gather 24 operand floats on lanes 0..7 (L1 hits — the warp just
            // pulled these lines for the copy).
            float a_l = 0.f, p_l = 0.f, i_l = 0.f;
            if (lane < 8) {
                a_l = xr[AX_START  + lane];
                p_l = xr[PC_START  + lane];
                i_l = xr[IMM_START + lane];
            }

            // Sequential n=0..7 accumulation mirrors XLA's unrolled
            // contraction. 16^n is a power of two -> multiply exact; only the
            // add rounds, so accumulation order is the one thing that matters.
            float imm = 0.f, pc = 0.f;
            int   ax  = 0;
            #pragma unroll
            for (int n = 0; n < 8; n++) {
                float an  = __shfl_sync(0xFFFFFFFFu, a_l, n);
                float pn  = __shfl_sync(0xFFFFFFFFu, p_l, n);
                float in_ = __shfl_sync(0xFFFFFFFFu, i_l, n);
                float pw  = (float)(1 << (4 * n));
                imm = __fadd_rn(imm, __fmul_rn(in_, pw));
                pc  = __fadd_rn(pc,  __fmul_rn(pn,  pw));
                ax += (int)an * (1 << (4 * n));   // trunc == astype(int32)
            }

            const bool az = (ax == 0);
            float new_pc, bt;
            const float pc8 = __fadd_rn(pc, 8.0f);
            if (jmp)      { new_pc = imm;            bt = 1.0f; }
            else if (bz)  { new_pc = az ? imm : pc8; bt = az ? 1.0f : 0.0f; }
            else if (bnz) { new_pc = az ? pc8 : imm; bt = az ? 0.0f : 1.0f; }
            else          { new_pc = pc;             bt = v1.w; /* unreachable */ }

            const int v = (int)new_pc;  // round-toward-zero == astype(int32)

            // Patch PC nibbles: cols 171..178 -> chunks 42(e3), 43(e0..3),
            // 44(e0..2); branch_taken col 203 -> chunk 50(e3).
            if (lane == 10) {           // chunk 42
                v1.w = (float)(v & 15);
            } else if (lane == 11) {    // chunk 43
                v1.x = (float)((v >> 4)  & 15);
                v1.y = (float)((v >> 8)  & 15);
                v1.z = (float)((v >> 12) & 15);
                v1.w = (float)((v >> 16) & 15);
            } else if (lane == 12) {    // chunk 44
                v1.x = (float)((v >> 20) & 15);
                v1.y = (float)((v >> 24) & 15);
                v1.z = (float)((v >> 28) & 15);
            } else if (lane == 18) {    // chunk 50
                v1.w = bt;
            }
        }
        // flags == 0: verbatim copy (reference early-return)

        yv[lane] = v0;
        if (lane < 20) yv[32 + lane] = v1;
    }
}

extern "C" void kernel_launch(void* const* d_in, const int* in_sizes, int n_in,
                              void* d_out, int out_size) {
    const float* x = (const float*)d_in[0];
    float*       y = (float*)d_out;
    int nrows = in_sizes[0] / NCOLS;

    fused_kernel<<<GRID, THREADS>>>(x, y, nrows);
}

// round 14
// speedup vs baseline: 1.0044x; 1.0044x over previous
#include <cuda_runtime.h>

// Layout constants (columns within the 208-wide feature dim)
#define NCOLS        208
#define OPCODE_START 88
#define AX_START     163
#define PC_START     171
#define IMM_START    195
#define BRANCH_TAKEN 203
// opcode offsets
#define OP_JMP 2
#define OP_BZ  4
#define OP_BNZ 5

// Persistent single-wave grid: 4 blocks/SM x 148 SMs. launch_bounds(256,4)
// caps regs at 64 -> co-residency of all 592 blocks is guaranteed on any
// sm_103a part (148 or 152 SMs), so the grid barrier below cannot deadlock.
#define GRID    592
#define THREADS 256
#define NWARPS  (GRID * (THREADS / 32))

__device__ unsigned g_partials[GRID];
// Monotone arrival counter. Zero at module load; NEVER reset. Each kernel
// execution performs exactly GRID atomicAdds, so a block computes its replay's
// barrier target from its own ticket: target = ticket - ticket%GRID + GRID.
// Deterministic across the correctness run and every graph replay.
__device__ unsigned g_arrive;

__global__ void __launch_bounds__(THREADS, 4)
fused_kernel(const float* __restrict__ x, float* __restrict__ y, int nrows)
{
    __shared__ unsigned s_warp[THREADS / 32];
    __shared__ unsigned s_target;
    __shared__ unsigned s_flags;

    const int tid  = threadIdx.x;
    const int gtid = blockIdx.x * THREADS + tid;

    // ---------------- Phase A: opcode scan (1 row/thread, grid-stride) -----
    unsigned f = 0u;
    for (int r = gtid; r < nrows; r += GRID * THREADS) {
        const float* xr = x + (size_t)r * NCOLS + OPCODE_START;
        if (xr[OP_JMP] > 0.5f) f |= 1u;
        if (xr[OP_BZ]  > 0.5f) f |= 2u;
        if (xr[OP_BNZ] > 0.5f) f |= 4u;
    }
    f = __reduce_or_sync(0xFFFFFFFFu, f);
    if ((tid & 31) == 0) s_warp[tid >> 5] = f;
    __syncthreads();

    if (tid == 0) {
        unsigned bf = 0u;
        #pragma unroll
        for (int w = 0; w < THREADS / 32; w++) bf |= s_warp[w];
        g_partials[blockIdx.x] = bf;        // unconditional -> no reset needed
        __threadfence();                    // release partial before arriving
        unsigned ticket = atomicAdd(&g_arrive, 1u);
        s_target = ticket - (ticket % GRID) + GRID;
    }
    __syncthreads();

    // ---------------- Reset-free grid barrier ------------------------------
    if (tid == 0) {
        const unsigned target = s_target;
        unsigned cur;
        do {
            asm volatile("ld.global.acquire.gpu.u32 %0, [%1];"
                         : "=r"(cur) : "l"(&g_arrive));
        } while (cur < target);
    }
    __syncthreads();   // acquire-ld + syncthreads orders partials for the block

    // OR the 592 partials (warp 0, L2-hot broadcast reads)
    if (tid < 32) {
        unsigned acc = 0u;
        for (int i = tid; i < GRID; i += 32) acc |= g_partials[i];
        acc = __reduce_or_sync(0xFFFFFFFFu, acc);
        if (tid == 0) s_flags = acc;
    }
    __syncthreads();
    const unsigned flags = s_flags;

    const bool jmp = (flags & 1u) != 0u;
    const bool bz  = (flags & 2u) != 0u;
    const bool bnz = (flags & 4u) != 0u;

    // ---------------- Phase B: warp-per-row copy + in-register patch -------
    const int gwarp = gtid >> 5;
    const int lane  = tid & 31;

    for (int row = gwarp; row < nrows; row += NWARPS) {
        const float*  xr = x + (size_t)row * NCOLS;
        float*        yr = y + (size_t)row * NCOLS;
        const float4* xv = (const float4*)xr;
        float4*       yv = (float4*)yr;

        // Bulk row copy: 52 float4 chunks (208 floats).
        float4 v0 = xv[lane];
        float4 v1;
        if (lane < 20) v1 = xv[32 + lane];

        if (flags != 0u) {
            // Gather 24 operand floats on lanes 0..7 (L1 hits — the warp just
            // pulled these lines for the copy).
            float a_l = 0.f, p_l = 0.f, i_l = 0.f;
            if (lane < 8) {
                a_l = xr[AX_START  + lane];
                p_l = xr[PC_START  + lane];
                i_l = xr[IMM_START + lane];
            }

            // Sequential n=0..7 accumulation mirrors XLA's unrolled
            // contraction. 16^n is a power of two -> multiply exact; only the
            // add rounds, so accumulation order is the one thing that matters.
            float imm = 0.f, pc = 0.f;
            int   ax  = 0;
            #pragma unroll
            for (int n = 0; n < 8; n++) {
                float an  = __shfl_sync(0xFFFFFFFFu, a_l, n);
                float pn  = __shfl_sync(0xFFFFFFFFu, p_l, n);
                float in_ = __shfl_sync(0xFFFFFFFFu, i_l, n);
                float pw  = (float)(1 << (4 * n));
                imm = __fadd_rn(imm, __fmul_rn(in_, pw));
                pc  = __fadd_rn(pc,  __fmul_rn(pn,  pw));
                ax += (int)an * (1 << (4 * n));   // trunc == astype(int32)
            }

            const bool az = (ax == 0);
            float new_pc, bt;
            const float pc8 = __fadd_rn(pc, 8.0f);
            if (jmp)      { new_pc = imm;            bt = 1.0f; }
            else if (bz)  { new_pc = az ? imm : pc8; bt = az ? 1.0f : 0.0f; }
            else if (bnz) { new_pc = az ? pc8 : imm; bt = az ? 0.0f : 1.0f; }
            else          { new_pc = pc;             bt = v1.w; /* unreachable */ }

            const int v = (int)new_pc;  // round-toward-zero == astype(int32)

            // Patch PC nibbles: cols 171..178 -> chunks 42(e3), 43(e0..3),
            // 44(e0..2); branch_taken col 203 -> chunk 50(e3).
            if (lane == 10) {           // chunk 42
                v1.w = (float)(v & 15);
            } else if (lane == 11) {    // chunk 43
                v1.x = (float)((v >> 4)  & 15);
                v1.y = (float)((v >> 8)  & 15);
                v1.z = (float)((v >> 12) & 15);
                v1.w = (float)((v >> 16) & 15);
            } else if (lane == 12) {    // chunk 44
                v1.x = (float)((v >> 20) & 15);
                v1.y = (float)((v >> 24) & 15);
                v1.z = (float)((v >> 28) & 15);
            } else if (lane == 18) {    // chunk 50
                v1.w = bt;
            }
        }
        // flags == 0: verbatim copy (reference early-return)

        yv[lane] = v0;
        if (lane < 20) yv[32 + lane] = v1;
    }
}

extern "C" void kernel_launch(void* const* d_in, const int* in_sizes, int n_in,
                              void* d_out, int out_size) {
    const float* x = (const float*)d_in[0];
    float*       y = (float*)d_out;
    int nrows = in_sizes[0] / NCOLS;

    fused_kernel<<<GRID, THREADS>>>(x, y, nrows);
}

// round 15
// speedup vs baseline: 1.1516x; 1.1465x over previous
#include <cuda_runtime.h>

// Layout constants (columns within the 208-wide feature dim)
#define NCOLS        208
#define OPCODE_START 88
// opcode offsets
#define OP_JMP 2
#define OP_BZ  4
#define OP_BNZ 5

#define SCAN_GRID    512
#define SCAN_THREADS 256

__device__ unsigned g_partials[SCAN_GRID];
// Monotone arrival counter: zero at module load, NEVER reset. Each scan
// execution adds exactly SCAN_GRID, so the last arrival of any run satisfies
// (ticket+1) % SCAN_GRID == 0. Deterministic across correctness run + replays.
__device__ unsigned g_arrive;
__device__ unsigned g_flags;

// Kernel 1: opcode scan. Each block ORs its rows' flags, stores its partial
// unconditionally (-> no reset kernel), and the LAST block to arrive reduces
// the partials into g_flags. No spin-wait anywhere -> no deadlock risk.
__global__ void __launch_bounds__(SCAN_THREADS)
scan_kernel(const float* __restrict__ x, int nrows)
{
    __shared__ unsigned s_warp[SCAN_THREADS / 32];
    __shared__ unsigned s_last;

    const int tid = threadIdx.x;
    unsigned f = 0u;
    for (int r = blockIdx.x * SCAN_THREADS + tid; r < nrows;
         r += SCAN_GRID * SCAN_THREADS) {
        const float* xr = x + (size_t)r * NCOLS + OPCODE_START;
        if (xr[OP_JMP] > 0.5f) f |= 1u;
        if (xr[OP_BZ]  > 0.5f) f |= 2u;
        if (xr[OP_BNZ] > 0.5f) f |= 4u;
    }
    f = __reduce_or_sync(0xFFFFFFFFu, f);
    if ((tid & 31) == 0) s_warp[tid >> 5] = f;
    __syncthreads();

    if (tid == 0) {
        unsigned bf = 0u;
        #pragma unroll
        for (int w = 0; w < SCAN_THREADS / 32; w++) bf |= s_warp[w];
        g_partials[blockIdx.x] = bf;
        __threadfence();                 // release partial before arriving
        unsigned ticket;
        asm volatile("atom.global.acq_rel.gpu.add.u32 %0, [%1], %2;"
                     : "=r"(ticket) : "l"(&g_arrive), "r"(1u) : "memory");
        s_last = (((ticket + 1u) % SCAN_GRID) == 0u) ? 1u : 0u;
    }
    __syncthreads();

    if (s_last && tid < 32) {            // last block: warp 0 reduces partials
        unsigned acc = 0u;
        #pragma unroll 4
        for (int i = tid; i < SCAN_GRID; i += 32) acc |= g_partials[i];
        acc = __reduce_or_sync(0xFFFFFFFFu, acc);
        if (tid == 0) g_flags = acc;     // unconditional store, no reset needed
    }
}

// Kernel 2: one warp per row. Streaming float4 copy; the 24 operand floats
// (AX/PC/IMM) are harvested from the already-loaded v1 registers via shuffles
// (AX: lane8.w, lane9.xyzw, lane10.xyz | PC: lane10.w, lane11.xyzw, lane12.xyz
//  | IMM: lane16.w, lane17.xyzw, lane18.xyz), so no memory is touched twice
// and .cs streaming hints are safe everywhere.
__global__ void __launch_bounds__(256)
apply_kernel(const float* __restrict__ x, float* __restrict__ y, int nrows)
{
    const int gw   = (blockIdx.x * blockDim.x + threadIdx.x) >> 5;
    const int lane = threadIdx.x & 31;
    if (gw >= nrows) return;

    const float4* xv = (const float4*)(x + (size_t)gw * NCOLS);
    float4*       yv = (float4*)(y + (size_t)gw * NCOLS);

    // Bulk row copy: 52 float4 chunks (208 floats), streaming loads.
    float4 v0 = __ldcs(xv + lane);
    float4 v1 = make_float4(0.f, 0.f, 0.f, 0.f);
    if (lane < 20) v1 = __ldcs(xv + 32 + lane);

    const unsigned flags = g_flags;

    if (flags != 0u) {
        const unsigned m = 0xFFFFFFFFu;
        // Operand broadcast straight out of v1 registers.
        float a0 = __shfl_sync(m, v1.w, 8);
        float a1 = __shfl_sync(m, v1.x, 9),  a2 = __shfl_sync(m, v1.y, 9);
        float a3 = __shfl_sync(m, v1.z, 9),  a4 = __shfl_sync(m, v1.w, 9);
        float a5 = __shfl_sync(m, v1.x, 10), a6 = __shfl_sync(m, v1.y, 10);
        float a7 = __shfl_sync(m, v1.z, 10);

        float p0 = __shfl_sync(m, v1.w, 10);
        float p1 = __shfl_sync(m, v1.x, 11), p2 = __shfl_sync(m, v1.y, 11);
        float p3 = __shfl_sync(m, v1.z, 11), p4 = __shfl_sync(m, v1.w, 11);
        float p5 = __shfl_sync(m, v1.x, 12), p6 = __shfl_sync(m, v1.y, 12);
        float p7 = __shfl_sync(m, v1.z, 12);

        float i0 = __shfl_sync(m, v1.w, 16);
        float i1 = __shfl_sync(m, v1.x, 17), i2 = __shfl_sync(m, v1.y, 17);
        float i3 = __shfl_sync(m, v1.z, 17), i4 = __shfl_sync(m, v1.w, 17);
        float i5 = __shfl_sync(m, v1.x, 18), i6 = __shfl_sync(m, v1.y, 18);
        float i7 = __shfl_sync(m, v1.z, 18);

        // Sequential n=0..7 accumulation mirrors XLA's unrolled contraction.
        // 16^n is a power of two -> multiplies exact; only add order matters.
        const float aops[8] = {a0,a1,a2,a3,a4,a5,a6,a7};
        const float pops[8] = {p0,p1,p2,p3,p4,p5,p6,p7};
        const float iops[8] = {i0,i1,i2,i3,i4,i5,i6,i7};
        float imm = 0.f, pc = 0.f;
        int   ax  = 0;
        #pragma unroll
        for (int n = 0; n < 8; n++) {
            const float pw = (float)(1 << (4 * n));
            imm = __fadd_rn(imm, __fmul_rn(iops[n], pw));
            pc  = __fadd_rn(pc,  __fmul_rn(pops[n], pw));
            ax += (int)aops[n] * (1 << (4 * n));   // trunc == astype(int32)
        }

        const bool jmp = (flags & 1u) != 0u;
        const bool bz  = (flags & 2u) != 0u;
        const bool bnz = (flags & 4u) != 0u;
        const bool az  = (ax == 0);

        float new_pc, bt;
        const float pc8 = __fadd_rn(pc, 8.0f);
        if (jmp)      { new_pc = imm;            bt = 1.0f; }
        else if (bz)  { new_pc = az ? imm : pc8; bt = az ? 1.0f : 0.0f; }
        else if (bnz) { new_pc = az ? pc8 : imm; bt = az ? 0.0f : 1.0f; }
        else          { new_pc = pc;             bt = 0.0f; /* unreachable */ }

        const int v = (int)new_pc;   // round-toward-zero == astype(int32)

        // Patch PC nibbles: cols 171..178 -> chunks 42(e3), 43(e0..3),
        // 44(e0..2); branch_taken col 203 -> chunk 50(e3).
        if (lane == 10) {
            v1.w = (float)(v & 15);
        } else if (lane == 11) {
            v1.x = (float)((v >> 4)  & 15);
            v1.y = (float)((v >> 8)  & 15);
            v1.z = (float)((v >> 12) & 15);
            v1.w = (float)((v >> 16) & 15);
        } else if (lane == 12) {
            v1.x = (float)((v >> 20) & 15);
            v1.y = (float)((v >> 24) & 15);
            v1.z = (float)((v >> 28) & 15);
        } else if (lane == 18) {
            v1.w = bt;
        }
    }
    // flags == 0: verbatim copy (reference early-return)

    __stcs(yv + lane, v0);
    if (lane < 20) __stcs(yv + 32 + lane, v1);
}

extern "C" void kernel_launch(void* const* d_in, const int* in_sizes, int n_in,
                              void* d_out, int out_size) {
    const float* x = (const float*)d_in[0];
    float*       y = (float*)d_out;
    int nrows = in_sizes[0] / NCOLS;

    scan_kernel<<<SCAN_GRID, SCAN_THREADS>>>(x, nrows);

    int rows_per_block = 256 / 32;
    int blocks = (nrows + rows_per_block - 1) / rows_per_block;
    apply_kernel<<<blocks, 256>>>(x, y, nrows);
}